// round 12
// baseline (speedup 1.0000x reference)
#include <cuda_runtime.h>
#include <cuda_fp16.h>
#include <cstdint>

// Problem constants
#define NN      50000
#define NE      800000
#define D       128
#define DH      512
#define TM      128
#define THREADS 256
#define NT      (NE / TM)        // 6250 tiles

// update/precompute strides (halves; word-stride mod 32 == 4 / 8)
#define HS2     136
#define WS2     136
#define SA2     264
#define WU2     264
#define PS      132
// edge kernel strides (halves)
#define US      72               // unit tile [128][64+8]
#define WSE     520              // resident W2m [128][512+8]

__device__ float  g_agg[NN * D];
__device__ __half g_Ph[NN * DH];        // x @ W1m_top + b1m
__device__ __half g_Qh[NN * DH];        // x @ W1m_bot
__device__ __half g_W1mh[DH * 256];     // [n=512][k=256]
__device__ __half g_W2mh[D * DH];       // [n=128][k=512]
__device__ __half g_W1uh[DH * 256];     // [n=512][k=256]
__device__ __half g_W2uh[D * DH];       // [n=128][k=512]

// smem layouts
#define SZ_H    (TM * HS2 * 2)
#define SZ_W    (TM * WS2 * 2)
#define SZ_A2   (TM * SA2 * 2)
#define SZ_WU   (TM * WU2 * 2)
#define PRE_SMEM  (SZ_H + SZ_W)
#define UPD_SMEM  (SZ_A2 + SZ_H + SZ_WU)
// edge: W resident + 2x(H,Q) unit buffers + 2x idx
#define E_W     0
#define E_H0    133120
#define E_H1    151552
#define E_Q0    169984
#define E_Q1    188416
#define E_TGT   206848
#define E_SRC   207872
#define EDGE_SMEM 208896

__global__ void zero_agg_kernel() {
    float4 z = make_float4(0.f, 0.f, 0.f, 0.f);
    int total = NN * D / 4;
    for (int p = blockIdx.x * blockDim.x + threadIdx.x; p < total;
         p += gridDim.x * blockDim.x)
        ((float4*)g_agg)[p] = z;
}

// One-time: transpose all weights to fp16, n-major (k contiguous).
__global__ void prep_weights(const float* __restrict__ W1m, const float* __restrict__ W2m,
                             const float* __restrict__ W1u, const float* __restrict__ W2u) {
    const int total = (131072 + 65536 + 131072 + 65536) / 2;
    for (int t = blockIdx.x * blockDim.x + threadIdx.x; t < total;
         t += gridDim.x * blockDim.x) {
        int idx = t;
        if (idx < 65536) {
            int n = idx >> 7, kk = (idx & 127) * 2;
            *(half2*)&g_W1mh[n * 256 + kk] =
                __floats2half2_rn(W1m[kk * 512 + n], W1m[(kk + 1) * 512 + n]);
        } else if (idx < 98304) { idx -= 65536;
            int n = idx >> 8, kk = (idx & 255) * 2;
            *(half2*)&g_W2mh[n * 512 + kk] =
                __floats2half2_rn(W2m[kk * 128 + n], W2m[(kk + 1) * 128 + n]);
        } else if (idx < 163840) { idx -= 98304;
            int n = idx >> 7, kk = (idx & 127) * 2;
            *(half2*)&g_W1uh[n * 256 + kk] =
                __floats2half2_rn(W1u[kk * 512 + n], W1u[(kk + 1) * 512 + n]);
        } else { idx -= 163840;
            int n = idx >> 8, kk = (idx & 255) * 2;
            *(half2*)&g_W2uh[n * 512 + kk] =
                __floats2half2_rn(W2u[kk * 128 + n], W2u[(kk + 1) * 128 + n]);
        }
    }
}

__device__ __forceinline__ int clamp_idx(int v) {
    v = v < 0 ? 0 : v;
    return v >= NN ? NN - 1 : v;
}
__device__ __forceinline__ uint32_t smem_u32(const void* p) {
    uint32_t a;
    asm("{ .reg .u64 t; cvta.to.shared.u64 t, %1; cvt.u32.u64 %0, t; }"
        : "=r"(a) : "l"(p));
    return a;
}
__device__ __forceinline__ uint2 f4_to_h4(float4 v) {
    half2 lo = __floats2half2_rn(v.x, v.y);
    half2 hi = __floats2half2_rn(v.z, v.w);
    uint2 r; r.x = *(uint32_t*)&lo; r.y = *(uint32_t*)&hi;
    return r;
}
__device__ __forceinline__ uint32_t f2_to_h2(float a, float b) {
    half2 h = __floats2half2_rn(a, b);
    return *(uint32_t*)&h;
}
__device__ __forceinline__ uint32_t hadd2_relu(uint32_t a, uint32_t b) {
    half2 r = __hmax2(__hadd2(*(half2*)&a, *(half2*)&b), __float2half2_rn(0.f));
    return *(uint32_t*)&r;
}

__device__ __forceinline__ void cp16(uint32_t dst, const void* src) {
    asm volatile("cp.async.cg.shared.global [%0], [%1], 16;"
                 :: "r"(dst), "l"(src) : "memory");
}
#define CP_COMMIT()   asm volatile("cp.async.commit_group;" ::: "memory")
#define CP_WAIT1()    asm volatile("cp.async.wait_group 1;" ::: "memory")
#define CP_WAIT_ALL() asm volatile("cp.async.wait_all;" ::: "memory")

__device__ __forceinline__ void mma_f16(float c[4],
                                        uint32_t a0, uint32_t a1, uint32_t a2, uint32_t a3,
                                        uint32_t b0, uint32_t b1) {
    asm volatile(
        "mma.sync.aligned.m16n8k16.row.col.f32.f16.f16.f32 "
        "{%0,%1,%2,%3}, {%4,%5,%6,%7}, {%8,%9}, {%0,%1,%2,%3};\n"
        : "+f"(c[0]), "+f"(c[1]), "+f"(c[2]), "+f"(c[3])
        : "r"(a0), "r"(a1), "r"(a2), "r"(a3), "r"(b0), "r"(b1));
}

// One k16 step, separate A/B k-offsets and strides. Warp tile 32x64.
__device__ __forceinline__ void mma_step2(const __half* __restrict__ sA, int LDA, int kA,
                                          const __half* __restrict__ sB, int LDB, int kB,
                                          int row0, int n0, int g, int tig,
                                          float acc[2][8][4]) {
    uint32_t a[2][4];
#pragma unroll
    for (int s = 0; s < 2; ++s) {
        const __half* r0p = sA + (row0 + s * 16 + g) * LDA + kA + 2 * tig;
        a[s][0] = *(const uint32_t*)r0p;
        a[s][1] = *(const uint32_t*)(r0p + 8 * LDA);
        a[s][2] = *(const uint32_t*)(r0p + 8);
        a[s][3] = *(const uint32_t*)(r0p + 8 * LDA + 8);
    }
    uint32_t b[8][2];
#pragma unroll
    for (int nt = 0; nt < 8; ++nt) {
        const __half* bb = sB + (n0 + nt * 8 + g) * LDB + kB + 2 * tig;
        b[nt][0] = *(const uint32_t*)bb;
        b[nt][1] = *(const uint32_t*)(bb + 8);
    }
#pragma unroll
    for (int s = 0; s < 2; ++s)
#pragma unroll
        for (int nt = 0; nt < 8; ++nt)
            mma_f16(acc[s][nt], a[s][0], a[s][1], a[s][2], a[s][3],
                    b[nt][0], b[nt][1]);
}

// ============ Precompute: P = x@W1m[0:128] + b1m ; Q = x@W1m[128:256] (fp16 out) ============
__global__ __launch_bounds__(THREADS, 2)
void precompute_kernel(const float* __restrict__ x,
                       const float* __restrict__ b1m) {
    extern __shared__ char smem[];
    __half* sA = (__half*)smem;
    __half* sW = (__half*)(smem + SZ_H);

    const int tid = threadIdx.x;
    const int lane = tid & 31;
    const int wid = tid >> 5;
    const int g = lane >> 2, tig = lane & 3;
    const int row0 = (wid >> 1) * 32, n0 = (wid & 1) * 64;
    const int rowBase = blockIdx.x * TM;
    const int half_sel = blockIdx.y;

    const float4* x4 = (const float4*)x;
#pragma unroll
    for (int p = 0; p < 16; ++p) {
        int f = p * THREADS + tid;
        int r = f >> 5, q = f & 31;
        int n = rowBase + r; if (n >= NN) n = 0;
        *(uint2*)(sA + r * HS2 + q * 4) = f4_to_h4(x4[(size_t)n * 32 + q]);
    }

    __half* outArr = half_sel ? g_Qh : g_Ph;

    for (int ch = 0; ch < 4; ++ch) {
        __syncthreads();
#pragma unroll
        for (int p = 0; p < 8; ++p) {
            int f = p * THREADS + tid;
            int n_ = f >> 4, q = f & 15;
            uint4 w = *(const uint4*)&g_W1mh[(size_t)(ch * 128 + n_) * 256
                                             + half_sel * 128 + q * 8];
            *(uint4*)(sW + n_ * WS2 + q * 8) = w;
        }
        __syncthreads();

        float acc[2][8][4];
#pragma unroll
        for (int nt = 0; nt < 8; ++nt) {
            float2 bv = half_sel ? make_float2(0.f, 0.f)
                                 : *(const float2*)&b1m[ch * 128 + n0 + nt * 8 + tig * 2];
#pragma unroll
            for (int s = 0; s < 2; ++s) {
                acc[s][nt][0] = bv.x; acc[s][nt][1] = bv.y;
                acc[s][nt][2] = bv.x; acc[s][nt][3] = bv.y;
            }
        }
#pragma unroll
        for (int ks = 0; ks < 8; ++ks)
            mma_step2(sA, HS2, ks * 16, sW, WS2, ks * 16, row0, n0, g, tig, acc);

#pragma unroll
        for (int s = 0; s < 2; ++s)
#pragma unroll
            for (int nt = 0; nt < 8; ++nt) {
                int r = row0 + s * 16 + g;
                int col = ch * 128 + n0 + nt * 8 + tig * 2;
                int n1 = rowBase + r, n2 = rowBase + r + 8;
                if (n1 < NN)
                    *(uint32_t*)&outArr[(size_t)n1 * DH + col] =
                        f2_to_h2(acc[s][nt][0], acc[s][nt][1]);
                if (n2 < NN)
                    *(uint32_t*)&outArr[(size_t)n2 * DH + col] =
                        f2_to_h2(acc[s][nt][2], acc[s][nt][3]);
            }
    }
}

// ============ Edge kernel: persistent, weight-stationary, cp.async pipelined ============
__global__ __launch_bounds__(THREADS, 1)
void edge_kernel(const int* __restrict__ edge_index,
                 const float* __restrict__ b2m) {
    extern __shared__ char smem[];
    const uint32_t sb = smem_u32(smem);
    __half* sW = (__half*)smem;                                   // [128][WSE]
    __half* sH[2] = { (__half*)(smem + E_H0), (__half*)(smem + E_H1) };
    __half* sQ[2] = { (__half*)(smem + E_Q0), (__half*)(smem + E_Q1) };
    const uint32_t hU[2] = { sb + E_H0, sb + E_H1 };
    const uint32_t qU[2] = { sb + E_Q0, sb + E_Q1 };
    int* sTgt[2] = { (int*)(smem + E_TGT), (int*)(smem + E_TGT) + 128 };
    int* sSrc[2] = { (int*)(smem + E_SRC), (int*)(smem + E_SRC) + 128 };

    const int tid = threadIdx.x;
    const int lane = tid & 31;
    const int wid = tid >> 5;
    const int g = lane >> 2, tig = lane & 3;
    const int row0 = (wid >> 1) * 32, n0 = (wid & 1) * 64;

    float2 bias[8];
#pragma unroll
    for (int nt = 0; nt < 8; ++nt)
        bias[nt] = *(const float2*)&b2m[n0 + nt * 8 + tig * 2];

    // stage whole W2m (group W)
    for (int c = tid; c < 8192; c += THREADS)
        cp16(sb + E_W + (c >> 6) * (WSE * 2) + (c & 63) * 16,
             g_W2mh + (size_t)(c >> 6) * 512 + (c & 63) * 8);
    CP_COMMIT();

    int tile = blockIdx.x;
    if (tid < 128) {
        sSrc[0][tid] = clamp_idx(edge_index[tile * TM + tid]);
        sTgt[0][tid] = clamp_idx(edge_index[NE + tile * TM + tid]);
    }
    __syncthreads();

    // issue unit 0 gathers (group G0)
#pragma unroll
    for (int p = 0; p < 4; ++p) {
        int slot = p * THREADS + tid;
        int r = slot >> 3, q = slot & 7;
        cp16(hU[0] + r * (US * 2) + q * 16, g_Ph + (size_t)sTgt[0][r] * DH + q * 8);
        cp16(qU[0] + r * (US * 2) + q * 16, g_Qh + (size_t)sSrc[0][r] * DH + q * 8);
    }
    CP_COMMIT();

    float acc[2][8][4];
#pragma unroll
    for (int s = 0; s < 2; ++s)
#pragma unroll
        for (int nt = 0; nt < 8; ++nt) {
            acc[s][nt][0] = bias[nt].x; acc[s][nt][1] = bias[nt].y;
            acc[s][nt][2] = bias[nt].x; acc[s][nt][3] = bias[nt].y;
        }

    int buf = 0, tb = 0;
    int nx_t = 0, nx_s = 0;

    for (; tile < NT; tile += gridDim.x) {
        int ntile = tile + gridDim.x;
        if (ntile >= NT) ntile = NT - 1;     // clamped prefetch (harmless)

        for (int u = 0; u < 8; ++u) {
            __syncthreads();     // previous unit's mma complete -> buf^1 free
            // issue gathers for next unit into buf^1
            {
                const int* pT = (u < 7) ? sTgt[tb] : sTgt[tb ^ 1];
                const int* pS = (u < 7) ? sSrc[tb] : sSrc[tb ^ 1];
                const int kc = (u < 7) ? (u + 1) * 64 : 0;
#pragma unroll
                for (int p = 0; p < 4; ++p) {
                    int slot = p * THREADS + tid;
                    int r = slot >> 3, q = slot & 7;
                    cp16(hU[buf ^ 1] + r * (US * 2) + q * 16,
                         g_Ph + (size_t)pT[r] * DH + kc + q * 8);
                    cp16(qU[buf ^ 1] + r * (US * 2) + q * 16,
                         g_Qh + (size_t)pS[r] * DH + kc + q * 8);
                }
            }
            CP_COMMIT();
            CP_WAIT1();          // current unit's data (own slots) arrived

            if (u == 0 && tid < 128) {   // prefetch next tile's indices
                nx_s = clamp_idx(edge_index[ntile * TM + tid]);
                nx_t = clamp_idx(edge_index[NE + ntile * TM + tid]);
            }
            if (u == 4 && tid < 128) {
                sSrc[tb ^ 1][tid] = nx_s;
                sTgt[tb ^ 1][tid] = nx_t;
            }

            // H = relu(P + Q) in place (each thread finalizes its own cp.async slots)
#pragma unroll
            for (int p = 0; p < 4; ++p) {
                int slot = p * THREADS + tid;
                int r = slot >> 3, q = slot & 7;
                uint4 a = *(uint4*)(sH[buf] + r * US + q * 8);
                uint4 b = *(uint4*)(sQ[buf] + r * US + q * 8);
                a.x = hadd2_relu(a.x, b.x);
                a.y = hadd2_relu(a.y, b.y);
                a.z = hadd2_relu(a.z, b.z);
                a.w = hadd2_relu(a.w, b.w);
                *(uint4*)(sH[buf] + r * US + q * 8) = a;
            }
            __syncthreads();     // H + W visible to all warps

#pragma unroll
            for (int ks = 0; ks < 4; ++ks)
                mma_step2(sH[buf], US, ks * 16, sW, WSE, u * 64 + ks * 16,
                          row0, n0, g, tig, acc);
            buf ^= 1;
        }

        // epilogue: scatter directly from registers (overlaps next tile's gathers)
#pragma unroll
        for (int s = 0; s < 2; ++s) {
            int r = row0 + s * 16 + g;
            float* d0 = g_agg + (size_t)sTgt[tb][r] * D + n0 + tig * 2;
            float* d1 = g_agg + (size_t)sTgt[tb][r + 8] * D + n0 + tig * 2;
#pragma unroll
            for (int nt = 0; nt < 8; ++nt) {
                asm volatile("red.global.add.v2.f32 [%0], {%1,%2};" ::
                    "l"(d0 + nt * 8), "f"(acc[s][nt][0]), "f"(acc[s][nt][1]) : "memory");
                asm volatile("red.global.add.v2.f32 [%0], {%1,%2};" ::
                    "l"(d1 + nt * 8), "f"(acc[s][nt][2]), "f"(acc[s][nt][3]) : "memory");
            }
        }
#pragma unroll
        for (int s = 0; s < 2; ++s)
#pragma unroll
            for (int nt = 0; nt < 8; ++nt) {
                acc[s][nt][0] = bias[nt].x; acc[s][nt][1] = bias[nt].y;
                acc[s][nt][2] = bias[nt].x; acc[s][nt][3] = bias[nt].y;
            }
        tb ^= 1;
    }
    CP_WAIT_ALL();   // drain trailing prefetch before exit
}

// ============ Update kernel: out = relu([x|agg]@W1u+b1u)@W2u+b2u ============
__global__ __launch_bounds__(THREADS, 1)
void update_kernel(const float* __restrict__ x,
                   const float* __restrict__ b1, const float* __restrict__ b2,
                   float* __restrict__ outp) {
    extern __shared__ char smem[];
    __half* sA = (__half*)smem;
    __half* sH = (__half*)(smem + SZ_A2);
    __half* sW = (__half*)(smem + SZ_A2 + SZ_H);
    float* perm = (float*)smem;

    const int tid = threadIdx.x;
    const int lane = tid & 31;
    const int wid = tid >> 5;
    const int g = lane >> 2, tig = lane & 3;
    const int row0 = (wid >> 1) * 32, n0 = (wid & 1) * 64;
    const int ty = tid >> 4, tx = tid & 15;
    const int rowBase = blockIdx.x * TM;

    const float4* x4 = (const float4*)x;
    const float4* agg4 = (const float4*)g_agg;
#pragma unroll
    for (int p = 0; p < 32; ++p) {
        int f = p * THREADS + tid;
        int r = f >> 6, q = f & 63;
        int n = rowBase + r; if (n >= NN) n = 0;
        float4 v = (q < 32) ? x4[(size_t)n * 32 + q] : agg4[(size_t)n * 32 + (q - 32)];
        *(uint2*)(sA + r * SA2 + q * 4) = f4_to_h4(v);
    }

    float accO[2][8][4];
#pragma unroll
    for (int nt = 0; nt < 8; ++nt) {
        float2 bv = *(const float2*)&b2[n0 + nt * 8 + tig * 2];
#pragma unroll
        for (int s = 0; s < 2; ++s) {
            accO[s][nt][0] = bv.x; accO[s][nt][1] = bv.y;
            accO[s][nt][2] = bv.x; accO[s][nt][3] = bv.y;
        }
    }

    for (int ch = 0; ch < 4; ++ch) {
        __syncthreads();
#pragma unroll
        for (int p = 0; p < 16; ++p) {
            int f = p * THREADS + tid;
            int n_ = f >> 5, q = f & 31;
            uint4 w = *(const uint4*)&g_W1uh[(size_t)(ch * 128 + n_) * 256 + q * 8];
            *(uint4*)(sW + n_ * WU2 + q * 8) = w;
        }
        __syncthreads();

        float accH[2][8][4];
#pragma unroll
        for (int nt = 0; nt < 8; ++nt) {
            float2 bv = *(const float2*)&b1[ch * 128 + n0 + nt * 8 + tig * 2];
#pragma unroll
            for (int s = 0; s < 2; ++s) {
                accH[s][nt][0] = bv.x; accH[s][nt][1] = bv.y;
                accH[s][nt][2] = bv.x; accH[s][nt][3] = bv.y;
            }
        }
#pragma unroll
        for (int ks = 0; ks < 16; ++ks)
            mma_step2(sA, SA2, ks * 16, sW, WU2, ks * 16, row0, n0, g, tig, accH);

        __syncthreads();
#pragma unroll
        for (int s = 0; s < 2; ++s)
#pragma unroll
            for (int nt = 0; nt < 8; ++nt) {
                int r = row0 + s * 16 + g;
                int c = n0 + nt * 8 + tig * 2;
                *(uint32_t*)(sH + r * HS2 + c) =
                    f2_to_h2(fmaxf(accH[s][nt][0], 0.f), fmaxf(accH[s][nt][1], 0.f));
                *(uint32_t*)(sH + (r + 8) * HS2 + c) =
                    f2_to_h2(fmaxf(accH[s][nt][2], 0.f), fmaxf(accH[s][nt][3], 0.f));
            }
#pragma unroll
        for (int p = 0; p < 8; ++p) {
            int f = p * THREADS + tid;
            int n_ = f >> 4, q = f & 15;
            uint4 w = *(const uint4*)&g_W2uh[(size_t)n_ * DH + ch * 128 + q * 8];
            *(uint4*)(sW + n_ * WU2 + q * 8) = w;
        }
        __syncthreads();
#pragma unroll
        for (int ks = 0; ks < 8; ++ks)
            mma_step2(sH, HS2, ks * 16, sW, WU2, ks * 16, row0, n0, g, tig, accO);
    }

    __syncthreads();
#pragma unroll
    for (int s = 0; s < 2; ++s)
#pragma unroll
        for (int nt = 0; nt < 8; ++nt) {
            int r = row0 + s * 16 + g;
            int c = n0 + nt * 8 + tig * 2;
            *(float2*)&perm[r * PS + c] = make_float2(accO[s][nt][0], accO[s][nt][1]);
            *(float2*)&perm[(r + 8) * PS + c] = make_float2(accO[s][nt][2], accO[s][nt][3]);
        }
    __syncthreads();
#pragma unroll
    for (int i = 0; i < 8; ++i) {
        int r = ty * 8 + i;
        int n = rowBase + r;
        if (n < NN) {
            float4 v0 = *(float4*)&perm[r * PS + tx * 8];
            float4 v1 = *(float4*)&perm[r * PS + tx * 8 + 4];
            *(float4*)&outp[(size_t)n * D + tx * 8] = v0;
            *(float4*)&outp[(size_t)n * D + tx * 8 + 4] = v1;
        }
    }
}

extern "C" void kernel_launch(void* const* d_in, const int* in_sizes, int n_in,
                              void* d_out, int out_size) {
    const float* x   = (const float*)d_in[0];
    const int* ei    = (const int*)d_in[2];   // int32 (JAX x64 disabled)
    const float* W1m = (const float*)d_in[3];
    const float* b1m = (const float*)d_in[4];
    const float* W2m = (const float*)d_in[5];
    const float* b2m = (const float*)d_in[6];
    const float* W1u = (const float*)d_in[7];
    const float* b1u = (const float*)d_in[8];
    const float* W2u = (const float*)d_in[9];
    const float* b2u = (const float*)d_in[10];

    cudaFuncSetAttribute(precompute_kernel,
                         cudaFuncAttributeMaxDynamicSharedMemorySize, PRE_SMEM);
    cudaFuncSetAttribute(edge_kernel,
                         cudaFuncAttributeMaxDynamicSharedMemorySize, EDGE_SMEM);
    cudaFuncSetAttribute(update_kernel,
                         cudaFuncAttributeMaxDynamicSharedMemorySize, UPD_SMEM);

    zero_agg_kernel<<<256, 256>>>();
    prep_weights<<<192, 256>>>(W1m, W2m, W1u, W2u);

    dim3 pgrid((NN + TM - 1) / TM, 2);
    precompute_kernel<<<pgrid, THREADS, PRE_SMEM>>>(x, b1m);

    edge_kernel<<<148, THREADS, EDGE_SMEM>>>(ei, b2m);

    update_kernel<<<(NN + TM - 1) / TM, THREADS, UPD_SMEM>>>(
        x, b1u, b2u, (float*)d_out);
}

// round 13
// speedup vs baseline: 1.2026x; 1.2026x over previous
#include <cuda_runtime.h>
#include <cuda_fp16.h>
#include <cstdint>

// Problem constants
#define NN      50000
#define NE      800000
#define D       128
#define DH      512
#define TM      128
#define THREADS 256
#define NT      (NE / TM)        // 6250 tiles

// strides in halves; word-stride mod 32 == 4 -> LDSM-phase conflict-free
#define HS2     136
#define WS2     136
#define SA2     264
#define WU2     264
#define US      72               // edge P/Q unit [128][64+8]
#define PS      132              // f32 permute stride

__device__ float  g_agg[NN * D];
__device__ __half g_Ph[NN * DH];        // x @ W1m_top + b1m
__device__ __half g_Qh[NN * DH];        // x @ W1m_bot
__device__ __half g_W1mh[DH * 256];     // [n=512][k=256]
__device__ __half g_W2mh[D * DH];       // [n=128][k=512]
__device__ __half g_W1uh[DH * 256];     // [n=512][k=256]
__device__ __half g_W2uh[D * DH];       // [n=128][k=512]

// smem layouts
#define SZ_H    (TM * HS2 * 2)          // 34816
#define SZ_W    (TM * WS2 * 2)          // 34816
#define SZ_A2   (TM * SA2 * 2)          // 67584
#define SZ_WU   (TM * WU2 * 2)          // 67584
#define PRE_SMEM  (SZ_H + SZ_W)
#define UPD_SMEM  (SZ_A2 + SZ_H + SZ_WU)
// edge: W chunk + double-buffered P/Q units + idx
#define E_W     0
#define E_P0    34816
#define E_P1    53248
#define E_Q0    71680
#define E_Q1    90112
#define E_TGT   108544
#define E_SRC   109056
#define EDGE_SMEM 109568                // x2 CTAs = 219 KB/SM

__global__ void zero_agg_kernel() {
    float4 z = make_float4(0.f, 0.f, 0.f, 0.f);
    int total = NN * D / 4;
    for (int p = blockIdx.x * blockDim.x + threadIdx.x; p < total;
         p += gridDim.x * blockDim.x)
        ((float4*)g_agg)[p] = z;
}

// One-time: transpose all weights to fp16, n-major (k contiguous).
__global__ void prep_weights(const float* __restrict__ W1m, const float* __restrict__ W2m,
                             const float* __restrict__ W1u, const float* __restrict__ W2u) {
    const int total = (131072 + 65536 + 131072 + 65536) / 2;
    for (int t = blockIdx.x * blockDim.x + threadIdx.x; t < total;
         t += gridDim.x * blockDim.x) {
        int idx = t;
        if (idx < 65536) {
            int n = idx >> 7, kk = (idx & 127) * 2;
            *(half2*)&g_W1mh[n * 256 + kk] =
                __floats2half2_rn(W1m[kk * 512 + n], W1m[(kk + 1) * 512 + n]);
        } else if (idx < 98304) { idx -= 65536;
            int n = idx >> 8, kk = (idx & 255) * 2;
            *(half2*)&g_W2mh[n * 512 + kk] =
                __floats2half2_rn(W2m[kk * 128 + n], W2m[(kk + 1) * 128 + n]);
        } else if (idx < 163840) { idx -= 98304;
            int n = idx >> 7, kk = (idx & 127) * 2;
            *(half2*)&g_W1uh[n * 256 + kk] =
                __floats2half2_rn(W1u[kk * 512 + n], W1u[(kk + 1) * 512 + n]);
        } else { idx -= 163840;
            int n = idx >> 8, kk = (idx & 255) * 2;
            *(half2*)&g_W2uh[n * 512 + kk] =
                __floats2half2_rn(W2u[kk * 128 + n], W2u[(kk + 1) * 128 + n]);
        }
    }
}

__device__ __forceinline__ int clamp_idx(int v) {
    v = v < 0 ? 0 : v;
    return v >= NN ? NN - 1 : v;
}
__device__ __forceinline__ uint32_t smem_u32(const void* p) {
    uint32_t a;
    asm("{ .reg .u64 t; cvta.to.shared.u64 t, %1; cvt.u32.u64 %0, t; }"
        : "=r"(a) : "l"(p));
    return a;
}
__device__ __forceinline__ uint2 f4_to_h4(float4 v) {
    half2 lo = __floats2half2_rn(v.x, v.y);
    half2 hi = __floats2half2_rn(v.z, v.w);
    uint2 r; r.x = *(uint32_t*)&lo; r.y = *(uint32_t*)&hi;
    return r;
}
__device__ __forceinline__ uint32_t f2_to_h2(float a, float b) {
    half2 h = __floats2half2_rn(a, b);
    return *(uint32_t*)&h;
}
__device__ __forceinline__ uint32_t hadd2_relu(uint32_t a, uint32_t b) {
    half2 r = __hmax2(__hadd2(*(half2*)&a, *(half2*)&b), __float2half2_rn(0.f));
    return *(uint32_t*)&r;
}

__device__ __forceinline__ void cp16(uint32_t dst, const void* src) {
    asm volatile("cp.async.cg.shared.global [%0], [%1], 16;"
                 :: "r"(dst), "l"(src) : "memory");
}
#define CP_COMMIT()   asm volatile("cp.async.commit_group;" ::: "memory")
#define CP_WAIT1()    asm volatile("cp.async.wait_group 1;" ::: "memory")
#define CP_WAIT_ALL() asm volatile("cp.async.wait_all;" ::: "memory")

__device__ __forceinline__ void mma_f16(float c[4],
                                        uint32_t a0, uint32_t a1, uint32_t a2, uint32_t a3,
                                        uint32_t b0, uint32_t b1) {
    asm volatile(
        "mma.sync.aligned.m16n8k16.row.col.f32.f16.f16.f32 "
        "{%0,%1,%2,%3}, {%4,%5,%6,%7}, {%8,%9}, {%0,%1,%2,%3};\n"
        : "+f"(c[0]), "+f"(c[1]), "+f"(c[2]), "+f"(c[3])
        : "r"(a0), "r"(a1), "r"(a2), "r"(a3), "r"(b0), "r"(b1));
}

__device__ __forceinline__ void ldsm4(uint32_t r[4], uint32_t addr) {
    asm volatile("ldmatrix.sync.aligned.m8n8.x4.shared.b16 {%0,%1,%2,%3}, [%4];"
                 : "=r"(r[0]), "=r"(r[1]), "=r"(r[2]), "=r"(r[3]) : "r"(addr));
}

// One k16 step via ldmatrix.x4. baseA/baseB = smem BYTE addrs of tiles.
// LDA/LDB/k offsets in halves. Warp tile 32x64.
__device__ __forceinline__ void mma_step_l(uint32_t baseA, int LDA, int kA,
                                           uint32_t baseB, int LDB, int kB,
                                           int row0, int n0, int lane,
                                           float acc[2][8][4]) {
    const int aRow = lane & 15, aK = (lane >> 4) << 3;
    const int bRow = (lane & 7) + ((lane & 16) >> 1), bK = lane & 8;
    uint32_t a[2][4];
#pragma unroll
    for (int s = 0; s < 2; ++s)
        ldsm4(a[s], baseA + (uint32_t)((row0 + s * 16 + aRow) * LDA + kA + aK) * 2);
    uint32_t b[8][2];
#pragma unroll
    for (int np = 0; np < 4; ++np) {
        uint32_t r[4];
        ldsm4(r, baseB + (uint32_t)((n0 + np * 16 + bRow) * LDB + kB + bK) * 2);
        b[np * 2][0] = r[0]; b[np * 2][1] = r[1];
        b[np * 2 + 1][0] = r[2]; b[np * 2 + 1][1] = r[3];
    }
#pragma unroll
    for (int s = 0; s < 2; ++s)
#pragma unroll
        for (int nt = 0; nt < 8; ++nt)
            mma_f16(acc[s][nt], a[s][0], a[s][1], a[s][2], a[s][3],
                    b[nt][0], b[nt][1]);
}

// ============ Precompute: P = x@W1m[0:128] + b1m ; Q = x@W1m[128:256] (fp16 out) ============
__global__ __launch_bounds__(THREADS, 2)
void precompute_kernel(const float* __restrict__ x,
                       const float* __restrict__ b1m) {
    extern __shared__ char smem[];
    __half* sA = (__half*)smem;
    __half* sW = (__half*)(smem + SZ_H);
    const uint32_t aB = smem_u32(smem);
    const uint32_t wB = aB + SZ_H;

    const int tid = threadIdx.x;
    const int lane = tid & 31;
    const int wid = tid >> 5;
    const int tig = lane & 3, g = lane >> 2;
    const int row0 = (wid >> 1) * 32, n0 = (wid & 1) * 64;
    const int rowBase = blockIdx.x * TM;
    const int half_sel = blockIdx.y;

    const float4* x4 = (const float4*)x;
#pragma unroll
    for (int p = 0; p < 16; ++p) {
        int f = p * THREADS + tid;
        int r = f >> 5, q = f & 31;
        int n = rowBase + r; if (n >= NN) n = 0;
        *(uint2*)(sA + r * HS2 + q * 4) = f4_to_h4(x4[(size_t)n * 32 + q]);
    }

    __half* outArr = half_sel ? g_Qh : g_Ph;

    for (int ch = 0; ch < 4; ++ch) {
        __syncthreads();
#pragma unroll
        for (int p = 0; p < 8; ++p) {
            int f = p * THREADS + tid;
            int n_ = f >> 4, q = f & 15;
            uint4 w = *(const uint4*)&g_W1mh[(size_t)(ch * 128 + n_) * 256
                                             + half_sel * 128 + q * 8];
            *(uint4*)(sW + n_ * WS2 + q * 8) = w;
        }
        __syncthreads();

        float acc[2][8][4];
#pragma unroll
        for (int nt = 0; nt < 8; ++nt) {
            float2 bv = half_sel ? make_float2(0.f, 0.f)
                                 : *(const float2*)&b1m[ch * 128 + n0 + nt * 8 + tig * 2];
#pragma unroll
            for (int s = 0; s < 2; ++s) {
                acc[s][nt][0] = bv.x; acc[s][nt][1] = bv.y;
                acc[s][nt][2] = bv.x; acc[s][nt][3] = bv.y;
            }
        }
#pragma unroll
        for (int ks = 0; ks < 8; ++ks)
            mma_step_l(aB, HS2, ks * 16, wB, WS2, ks * 16, row0, n0, lane, acc);

#pragma unroll
        for (int s = 0; s < 2; ++s)
#pragma unroll
            for (int nt = 0; nt < 8; ++nt) {
                int r = row0 + s * 16 + g;
                int col = ch * 128 + n0 + nt * 8 + tig * 2;
                int n1 = rowBase + r, n2 = rowBase + r + 8;
                if (n1 < NN)
                    *(uint32_t*)&outArr[(size_t)n1 * DH + col] =
                        f2_to_h2(acc[s][nt][0], acc[s][nt][1]);
                if (n2 < NN)
                    *(uint32_t*)&outArr[(size_t)n2 * DH + col] =
                        f2_to_h2(acc[s][nt][2], acc[s][nt][3]);
            }
    }
}

// ============ Edge kernel: 2 CTA/SM, cp.async 64-col unit pipeline ============
__global__ __launch_bounds__(THREADS, 2)
void edge_kernel(const int* __restrict__ edge_index,
                 const float* __restrict__ b2m) {
    extern __shared__ char smem[];
    const uint32_t sb = smem_u32(smem);
    const uint32_t wB = sb + E_W;
    const uint32_t pB[2] = { sb + E_P0, sb + E_P1 };
    __half* sWh = (__half*)(smem + E_W);
    __half* sP[2] = { (__half*)(smem + E_P0), (__half*)(smem + E_P1) };
    __half* sQ[2] = { (__half*)(smem + E_Q0), (__half*)(smem + E_Q1) };
    const uint32_t qB[2] = { sb + E_Q0, sb + E_Q1 };
    int* sTgt = (int*)(smem + E_TGT);
    int* sSrc = (int*)(smem + E_SRC);
    float* perm = (float*)smem;

    const int tid = threadIdx.x;
    const int lane = tid & 31;
    const int wid = tid >> 5;
    const int tig = lane & 3, g = lane >> 2;
    const int row0 = (wid >> 1) * 32, n0 = (wid & 1) * 64;
    const int ty = tid >> 4, tx = tid & 15;
    const int tile = blockIdx.x;
    const int r0s = tid >> 3;       // own cp slot: rows r0s + p*32
    const int qs = tid & 7;         // own cp slot: 8-col group

    float2 bias[8];
#pragma unroll
    for (int nt = 0; nt < 8; ++nt)
        bias[nt] = *(const float2*)&b2m[n0 + nt * 8 + tig * 2];

    if (tid < 128) {
        sSrc[tid] = clamp_idx(edge_index[tile * TM + tid]);
        sTgt[tid] = clamp_idx(edge_index[NE + tile * TM + tid]);
    }
    __syncthreads();

    // issue unit 0 (k-cols 0..63) -> buffers[0]
#pragma unroll
    for (int p = 0; p < 4; ++p) {
        int r = r0s + p * 32;
        cp16(pB[0] + r * (US * 2) + qs * 16, g_Ph + (size_t)sTgt[r] * DH + qs * 8);
        cp16(qB[0] + r * (US * 2) + qs * 16, g_Qh + (size_t)sSrc[r] * DH + qs * 8);
    }
    CP_COMMIT();

    float acc[2][8][4];
#pragma unroll
    for (int s = 0; s < 2; ++s)
#pragma unroll
        for (int nt = 0; nt < 8; ++nt) {
            acc[s][nt][0] = bias[nt].x; acc[s][nt][1] = bias[nt].y;
            acc[s][nt][2] = bias[nt].x; acc[s][nt][3] = bias[nt].y;
        }

    for (int u = 0; u < 8; ++u) {
        const int buf = u & 1;
        __syncthreads();            // mma(u-1) done: sW + buf^1 reusable
        if ((u & 1) == 0) {
            // stage W2m chunk u/2: [n=128][k=128]
            const int ch = u >> 1;
#pragma unroll
            for (int p = 0; p < 8; ++p) {
                int f = p * THREADS + tid;
                int n_ = f >> 4, q = f & 15;
                uint4 w = *(const uint4*)&g_W2mh[(size_t)n_ * DH + ch * 128 + q * 8];
                *(uint4*)(sWh + n_ * WS2 + q * 8) = w;
            }
        }
        if (u < 7) {
            // prefetch unit u+1 into buf^1
            const int kc = (u + 1) * 64;
#pragma unroll
            for (int p = 0; p < 4; ++p) {
                int r = r0s + p * 32;
                cp16(pB[buf ^ 1] + r * (US * 2) + qs * 16,
                     g_Ph + (size_t)sTgt[r] * DH + kc + qs * 8);
                cp16(qB[buf ^ 1] + r * (US * 2) + qs * 16,
                     g_Qh + (size_t)sSrc[r] * DH + kc + qs * 8);
            }
            CP_COMMIT();
            CP_WAIT1();             // own unit-u data landed
        } else {
            CP_WAIT_ALL();
        }
        // H = relu(P + Q) in place (own slots only)
#pragma unroll
        for (int p = 0; p < 4; ++p) {
            int r = r0s + p * 32;
            uint4 a4 = *(uint4*)(sP[buf] + r * US + qs * 8);
            uint4 b4 = *(uint4*)(sQ[buf] + r * US + qs * 8);
            a4.x = hadd2_relu(a4.x, b4.x);
            a4.y = hadd2_relu(a4.y, b4.y);
            a4.z = hadd2_relu(a4.z, b4.z);
            a4.w = hadd2_relu(a4.w, b4.w);
            *(uint4*)(sP[buf] + r * US + qs * 8) = a4;
        }
        __syncthreads();            // H + W visible to all warps
        const int kb0 = (u & 1) * 64;   // k offset within current W chunk
#pragma unroll
        for (int ks = 0; ks < 4; ++ks)
            mma_step_l(pB[buf], US, ks * 16, wB, WS2, kb0 + ks * 16,
                       row0, n0, lane, acc);
    }

    // epilogue: permute through f32 overlay, coalesced v4 scatter
    __syncthreads();
#pragma unroll
    for (int s = 0; s < 2; ++s)
#pragma unroll
        for (int nt = 0; nt < 8; ++nt) {
            int r = row0 + s * 16 + g;
            int c = n0 + nt * 8 + tig * 2;
            *(float2*)&perm[r * PS + c] = make_float2(acc[s][nt][0], acc[s][nt][1]);
            *(float2*)&perm[(r + 8) * PS + c] = make_float2(acc[s][nt][2], acc[s][nt][3]);
        }
    __syncthreads();
#pragma unroll
    for (int i = 0; i < 8; ++i) {
        int r = ty * 8 + i;
        float4 v0 = *(float4*)&perm[r * PS + tx * 8];
        float4 v1 = *(float4*)&perm[r * PS + tx * 8 + 4];
        float* dst = g_agg + (size_t)sTgt[r] * D + tx * 8;
        asm volatile("red.global.add.v4.f32 [%0], {%1,%2,%3,%4};" ::
            "l"(dst), "f"(v0.x), "f"(v0.y), "f"(v0.z), "f"(v0.w) : "memory");
        asm volatile("red.global.add.v4.f32 [%0], {%1,%2,%3,%4};" ::
            "l"(dst + 4), "f"(v1.x), "f"(v1.y), "f"(v1.z), "f"(v1.w) : "memory");
    }
}

// ============ Update kernel: out = relu([x|agg]@W1u+b1u)@W2u+b2u ============
__global__ __launch_bounds__(THREADS, 1)
void update_kernel(const float* __restrict__ x,
                   const float* __restrict__ b1, const float* __restrict__ b2,
                   float* __restrict__ outp) {
    extern __shared__ char smem[];
    __half* sA = (__half*)smem;
    __half* sH = (__half*)(smem + SZ_A2);
    __half* sW = (__half*)(smem + SZ_A2 + SZ_H);
    float* perm = (float*)smem;
    const uint32_t aB = smem_u32(smem);
    const uint32_t hB = aB + SZ_A2;
    const uint32_t wB = aB + SZ_A2 + SZ_H;

    const int tid = threadIdx.x;
    const int lane = tid & 31;
    const int wid = tid >> 5;
    const int tig = lane & 3, g = lane >> 2;
    const int row0 = (wid >> 1) * 32, n0 = (wid & 1) * 64;
    const int ty = tid >> 4, tx = tid & 15;
    const int rowBase = blockIdx.x * TM;

    const float4* x4 = (const float4*)x;
    const float4* agg4 = (const float4*)g_agg;
#pragma unroll
    for (int p = 0; p < 32; ++p) {
        int f = p * THREADS + tid;
        int r = f >> 6, q = f & 63;
        int n = rowBase + r; if (n >= NN) n = 0;
        float4 v = (q < 32) ? x4[(size_t)n * 32 + q] : agg4[(size_t)n * 32 + (q - 32)];
        *(uint2*)(sA + r * SA2 + q * 4) = f4_to_h4(v);
    }

    float accO[2][8][4];
#pragma unroll
    for (int nt = 0; nt < 8; ++nt) {
        float2 bv = *(const float2*)&b2[n0 + nt * 8 + tig * 2];
#pragma unroll
        for (int s = 0; s < 2; ++s) {
            accO[s][nt][0] = bv.x; accO[s][nt][1] = bv.y;
            accO[s][nt][2] = bv.x; accO[s][nt][3] = bv.y;
        }
    }

    for (int ch = 0; ch < 4; ++ch) {
        __syncthreads();
#pragma unroll
        for (int p = 0; p < 16; ++p) {
            int f = p * THREADS + tid;
            int n_ = f >> 5, q = f & 31;
            uint4 w = *(const uint4*)&g_W1uh[(size_t)(ch * 128 + n_) * 256 + q * 8];
            *(uint4*)(sW + n_ * WU2 + q * 8) = w;
        }
        __syncthreads();

        float accH[2][8][4];
#pragma unroll
        for (int nt = 0; nt < 8; ++nt) {
            float2 bv = *(const float2*)&b1[ch * 128 + n0 + nt * 8 + tig * 2];
#pragma unroll
            for (int s = 0; s < 2; ++s) {
                accH[s][nt][0] = bv.x; accH[s][nt][1] = bv.y;
                accH[s][nt][2] = bv.x; accH[s][nt][3] = bv.y;
            }
        }
#pragma unroll
        for (int ks = 0; ks < 16; ++ks)
            mma_step_l(aB, SA2, ks * 16, wB, WU2, ks * 16, row0, n0, lane, accH);

        __syncthreads();
#pragma unroll
        for (int s = 0; s < 2; ++s)
#pragma unroll
            for (int nt = 0; nt < 8; ++nt) {
                int r = row0 + s * 16 + g;
                int c = n0 + nt * 8 + tig * 2;
                *(uint32_t*)(sH + r * HS2 + c) =
                    f2_to_h2(fmaxf(accH[s][nt][0], 0.f), fmaxf(accH[s][nt][1], 0.f));
                *(uint32_t*)(sH + (r + 8) * HS2 + c) =
                    f2_to_h2(fmaxf(accH[s][nt][2], 0.f), fmaxf(accH[s][nt][3], 0.f));
            }
#pragma unroll
        for (int p = 0; p < 8; ++p) {
            int f = p * THREADS + tid;
            int n_ = f >> 4, q = f & 15;
            uint4 w = *(const uint4*)&g_W2uh[(size_t)n_ * DH + ch * 128 + q * 8];
            *(uint4*)(sW + n_ * WU2 + q * 8) = w;
        }
        __syncthreads();
#pragma unroll
        for (int ks = 0; ks < 8; ++ks)
            mma_step_l(hB, HS2, ks * 16, wB, WU2, ks * 16, row0, n0, lane, accO);
    }

    __syncthreads();
#pragma unroll
    for (int s = 0; s < 2; ++s)
#pragma unroll
        for (int nt = 0; nt < 8; ++nt) {
            int r = row0 + s * 16 + g;
            int c = n0 + nt * 8 + tig * 2;
            *(float2*)&perm[r * PS + c] = make_float2(accO[s][nt][0], accO[s][nt][1]);
            *(float2*)&perm[(r + 8) * PS + c] = make_float2(accO[s][nt][2], accO[s][nt][3]);
        }
    __syncthreads();
#pragma unroll
    for (int i = 0; i < 8; ++i) {
        int r = ty * 8 + i;
        int n = rowBase + r;
        if (n < NN) {
            float4 v0 = *(float4*)&perm[r * PS + tx * 8];
            float4 v1 = *(float4*)&perm[r * PS + tx * 8 + 4];
            *(float4*)&outp[(size_t)n * D + tx * 8] = v0;
            *(float4*)&outp[(size_t)n * D + tx * 8 + 4] = v1;
        }
    }
}

extern "C" void kernel_launch(void* const* d_in, const int* in_sizes, int n_in,
                              void* d_out, int out_size) {
    const float* x   = (const float*)d_in[0];
    const int* ei    = (const int*)d_in[2];   // int32 (JAX x64 disabled)
    const float* W1m = (const float*)d_in[3];
    const float* b1m = (const float*)d_in[4];
    const float* W2m = (const float*)d_in[5];
    const float* b2m = (const float*)d_in[6];
    const float* W1u = (const float*)d_in[7];
    const float* b1u = (const float*)d_in[8];
    const float* W2u = (const float*)d_in[9];
    const float* b2u = (const float*)d_in[10];

    cudaFuncSetAttribute(precompute_kernel,
                         cudaFuncAttributeMaxDynamicSharedMemorySize, PRE_SMEM);
    cudaFuncSetAttribute(edge_kernel,
                         cudaFuncAttributeMaxDynamicSharedMemorySize, EDGE_SMEM);
    cudaFuncSetAttribute(update_kernel,
                         cudaFuncAttributeMaxDynamicSharedMemorySize, UPD_SMEM);

    zero_agg_kernel<<<256, 256>>>();
    prep_weights<<<192, 256>>>(W1m, W2m, W1u, W2u);

    dim3 pgrid((NN + TM - 1) / TM, 2);
    precompute_kernel<<<pgrid, THREADS, PRE_SMEM>>>(x, b1m);

    edge_kernel<<<NT, THREADS, EDGE_SMEM>>>(ei, b2m);

    update_kernel<<<(NN + TM - 1) / TM, THREADS, UPD_SMEM>>>(
        x, b1u, b2u, (float*)d_out);
}